// round 3
// baseline (speedup 1.0000x reference)
#include <cuda_runtime.h>
#include <math.h>

#define B_     4096
#define D_     512
#define H_     512
#define V_     128
#define MAXLEN 100
#define TH3    1536   // 3*H

// ------------------------- persistent device scratch -------------------------
__device__ float g_h0[2][B_ * H_];        // layer0 hidden, ping-pong
__device__ float g_h1[2][B_ * H_];        // layer1 hidden, ping-pong
__device__ float g_zc0p[B_ * TH3];        // z @ Wih0[:,H:]^T + bih0, gate-interleaved cols
__device__ float g_T0p[V_ * TH3];         // emb @ Wih0[:,:H]^T, gate-interleaved cols
__device__ float g_Whh0p[TH3 * H_];       // permuted: row j*3+g = Whh0[g*H+j]
__device__ float g_Wih1p[TH3 * H_];
__device__ float g_Whh1p[TH3 * H_];
__device__ float g_Wih0ep[TH3 * H_];      // permuted Wih0[:, :H]   (emb part)
__device__ float g_Wih0zp[TH3 * H_];      // permuted Wih0[:, H:]   (z part)
__device__ float g_bhh0p[TH3];
__device__ float g_bi1p[TH3];
__device__ float g_bh1p[TH3];
__device__ float g_bih0p[TH3];
__device__ float g_outWt[H_ * V_];        // out_W transposed: [k][v]
__device__ int   g_w[B_];                 // current token per row
__device__ int   g_eos[B_];               // eos flag per row

// --------- accurate, fast-math-immune exp / sigmoid / tanh (fp32, ~1 ulp) ---------
__device__ __forceinline__ float exp_acc(float x) {
    x = fminf(fmaxf(x, -87.0f), 88.0f);
    float k = rintf(x * 1.4426950408889634f);
    float f = fmaf(k, -0.693359375f, x);      // ln2_hi
    f = fmaf(k, 2.12194440e-4f, f);           // ln2_lo correction
    float z = f * f;
    float p = 1.9875691500e-4f;
    p = fmaf(p, f, 1.3981999507e-3f);
    p = fmaf(p, f, 8.3334519073e-3f);
    p = fmaf(p, f, 4.1665795894e-2f);
    p = fmaf(p, f, 1.6666665459e-1f);
    p = fmaf(p, f, 5.0000001201e-1f);
    float y = fmaf(p, z, f) + 1.0f;
    return __int_as_float(__float_as_int(y) + (((int)k) << 23));
}
__device__ __forceinline__ float sigmoidf_(float x) { return 1.0f / (1.0f + exp_acc(-x)); }
__device__ __forceinline__ float tanhf_(float x) {
    float e = exp_acc(2.0f * x);
    return (e - 1.0f) / (e + 1.0f);
}

// ------------------------- init: weight permutation -------------------------
__global__ void permute_kernel(const float* __restrict__ Wih0,
                               const float* __restrict__ Whh0,
                               const float* __restrict__ Wih1,
                               const float* __restrict__ Whh1,
                               const float* __restrict__ bih0,
                               const float* __restrict__ bhh0,
                               const float* __restrict__ bih1,
                               const float* __restrict__ bhh1,
                               const float* __restrict__ outW) {
    int idx = blockIdx.x * blockDim.x + threadIdx.x;
    if (idx < TH3 * H_) {
        int c = idx / H_;          // permuted row: j*3+g
        int k = idx - c * H_;
        int j = c / 3, g = c - 3 * (c / 3);
        int src = g * H_ + j;
        g_Whh0p[idx]  = Whh0[src * H_ + k];
        g_Wih1p[idx]  = Wih1[src * H_ + k];
        g_Whh1p[idx]  = Whh1[src * H_ + k];
        g_Wih0ep[idx] = Wih0[src * (H_ + D_) + k];
        g_Wih0zp[idx] = Wih0[src * (H_ + D_) + H_ + k];
        if (k == 0) {
            g_bhh0p[c] = bhh0[src];
            g_bi1p[c]  = bih1[src];
            g_bh1p[c]  = bhh1[src];
            g_bih0p[c] = bih0[src];
        }
    }
    if (idx < H_ * V_) {
        int k = idx / V_, v = idx - k * V_;
        g_outWt[idx] = outW[v * H_ + k];
    }
}

__global__ void init_state_kernel(float* __restrict__ xout, float* __restrict__ endp) {
    int b = blockIdx.x * blockDim.x + threadIdx.x;
    if (b < B_) {
        g_w[b]   = 1;        // bos token
        g_eos[b] = 0;
        if (endp) endp[b] = (float)MAXLEN;
        xout[b * MAXLEN] = 1.0f;
    }
}

// ------------------------- init GEMMs: C = A @ W^T (+bias) -------------------------
__global__ void __launch_bounds__(256) gemm_init_kernel(const float* __restrict__ A,
                                                        const float* __restrict__ Wext,
                                                        const float* __restrict__ biasext,
                                                        int mode) {
    const float* W;
    const float* bias;
    float* C;
    float* C2 = nullptr;
    int N;
    if (mode == 0)      { W = Wext;      bias = biasext;  C = g_h0[0]; C2 = g_h1[0]; N = H_;  }
    else if (mode == 1) { W = g_Wih0zp;  bias = g_bih0p;  C = g_zc0p;  N = TH3; }
    else                { W = g_Wih0ep;  bias = nullptr;  C = g_T0p;   N = TH3; }

    __shared__ float As[16][64];
    __shared__ float Bs[16][64];
    int bm = blockIdx.y * 64, bn = blockIdx.x * 64;
    int tid = threadIdx.x;
    int tx = tid & 15, ty = tid >> 4;
    float acc[4][4] = {};

    for (int kt = 0; kt < H_; kt += 16) {
        int r = tid >> 2, kc = (tid & 3) * 4;
        float4 va = *(const float4*)(A + (size_t)(bm + r) * H_ + kt + kc);
        float4 vb = *(const float4*)(W + (size_t)(bn + r) * H_ + kt + kc);
        As[kc + 0][r] = va.x; As[kc + 1][r] = va.y; As[kc + 2][r] = va.z; As[kc + 3][r] = va.w;
        Bs[kc + 0][r] = vb.x; Bs[kc + 1][r] = vb.y; Bs[kc + 2][r] = vb.z; Bs[kc + 3][r] = vb.w;
        __syncthreads();
#pragma unroll
        for (int kk = 0; kk < 16; kk++) {
            float a[4], b[4];
            *(float4*)a = *(const float4*)&As[kk][ty * 4];
            *(float4*)b = *(const float4*)&Bs[kk][tx * 4];
#pragma unroll
            for (int i = 0; i < 4; i++)
#pragma unroll
                for (int j = 0; j < 4; j++) acc[i][j] += a[i] * b[j];
        }
        __syncthreads();
    }
#pragma unroll
    for (int i = 0; i < 4; i++) {
        int row = bm + ty * 4 + i;
#pragma unroll
        for (int j = 0; j < 4; j++) {
            int col = bn + tx * 4 + j;
            float v = acc[i][j] + (bias ? bias[col] : 0.0f);
            C[(size_t)row * N + col] = v;
            if (C2) C2[(size_t)row * N + col] = v;
        }
    }
}

// ------------------------- step kernel 1: layer0 GRU -------------------------
__global__ void __launch_bounds__(256) layer0_kernel(int p) {
    const float* __restrict__ hcur  = g_h0[p ^ 1];
    float*       __restrict__ hnext = g_h0[p];
    __shared__ float As[16][128];
    __shared__ float Bs[16][96];

    int bm = blockIdx.y * 128;
    int bh = blockIdx.x * 32;    // h-index base
    int c0 = bh * 3;             // permuted col base
    int tid = threadIdx.x;
    int tx = tid & 15, ty = tid >> 4;
    float acc[8][6] = {};

    for (int kt = 0; kt < H_; kt += 16) {
        int r = tid >> 2, kc = (tid & 3) * 4;
        float4 v0 = *(const float4*)(hcur + (size_t)(bm + r) * H_ + kt + kc);
        float4 v1 = *(const float4*)(hcur + (size_t)(bm + r + 64) * H_ + kt + kc);
        As[kc + 0][r]      = v0.x; As[kc + 1][r]      = v0.y; As[kc + 2][r]      = v0.z; As[kc + 3][r]      = v0.w;
        As[kc + 0][r + 64] = v1.x; As[kc + 1][r + 64] = v1.y; As[kc + 2][r + 64] = v1.z; As[kc + 3][r + 64] = v1.w;
        float4 w0 = *(const float4*)(&g_Whh0p[(size_t)(c0 + r) * H_ + kt + kc]);
        Bs[kc + 0][r] = w0.x; Bs[kc + 1][r] = w0.y; Bs[kc + 2][r] = w0.z; Bs[kc + 3][r] = w0.w;
        if (tid < 128) {
            int r2 = 64 + (tid >> 2);
            float4 w1 = *(const float4*)(&g_Whh0p[(size_t)(c0 + r2) * H_ + kt + kc]);
            Bs[kc + 0][r2] = w1.x; Bs[kc + 1][r2] = w1.y; Bs[kc + 2][r2] = w1.z; Bs[kc + 3][r2] = w1.w;
        }
        __syncthreads();
#pragma unroll
        for (int kk = 0; kk < 16; kk++) {
            float a[8], b[6];
            *(float4*)&a[0] = *(const float4*)&As[kk][ty * 8];
            *(float4*)&a[4] = *(const float4*)&As[kk][ty * 8 + 4];
            *(float2*)&b[0] = *(const float2*)&Bs[kk][tx * 6];
            *(float2*)&b[2] = *(const float2*)&Bs[kk][tx * 6 + 2];
            *(float2*)&b[4] = *(const float2*)&Bs[kk][tx * 6 + 4];
#pragma unroll
            for (int i = 0; i < 8; i++)
#pragma unroll
                for (int j = 0; j < 6; j++) acc[i][j] += a[i] * b[j];
        }
        __syncthreads();
    }
#pragma unroll
    for (int i = 0; i < 8; i++) {
        int b = bm + ty * 8 + i;
        int wt = g_w[b];
        const float* Trow = &g_T0p[wt * TH3];
        const float* Zrow = &g_zc0p[(size_t)b * TH3];
#pragma unroll
        for (int hh = 0; hh < 2; hh++) {
            int j = bh + tx * 2 + hh;
            int c = j * 3;
            float gi0 = Trow[c]     + Zrow[c];
            float gi1 = Trow[c + 1] + Zrow[c + 1];
            float gi2 = Trow[c + 2] + Zrow[c + 2];
            float gh0 = acc[i][hh * 3 + 0] + g_bhh0p[c];
            float gh1 = acc[i][hh * 3 + 1] + g_bhh0p[c + 1];
            float gh2 = acc[i][hh * 3 + 2] + g_bhh0p[c + 2];
            float rg = sigmoidf_(gi0 + gh0);
            float zg = sigmoidf_(gi1 + gh1);
            float nn = tanhf_(gi2 + rg * gh2);
            float hp = hcur[(size_t)b * H_ + j];
            hnext[(size_t)b * H_ + j] = (1.0f - zg) * nn + zg * hp;
        }
    }
}

// ------------------------- step kernel 2: layer1 GRU (dual GEMM) -------------------------
__global__ void __launch_bounds__(256) layer1_kernel(int p) {
    const float* __restrict__ x     = g_h0[p];       // h_l0 (input of layer1)
    const float* __restrict__ hcur  = g_h1[p ^ 1];
    float*       __restrict__ hnext = g_h1[p];
    __shared__ float As1[16][128];
    __shared__ float As2[16][128];
    __shared__ float Bs1[16][48];
    __shared__ float Bs2[16][48];

    int bm = blockIdx.y * 128;
    int bh = blockIdx.x * 16;
    int c0 = bh * 3;
    int tid = threadIdx.x;
    int tx = tid & 15, ty = tid >> 4;
    float acc_i[8][3] = {};
    float acc_h[8][3] = {};

    for (int kt = 0; kt < H_; kt += 16) {
        int r = tid >> 2, kc = (tid & 3) * 4;
        float4 x0 = *(const float4*)(x    + (size_t)(bm + r) * H_ + kt + kc);
        float4 x1 = *(const float4*)(x    + (size_t)(bm + r + 64) * H_ + kt + kc);
        float4 h0v = *(const float4*)(hcur + (size_t)(bm + r) * H_ + kt + kc);
        float4 h1v = *(const float4*)(hcur + (size_t)(bm + r + 64) * H_ + kt + kc);
        As1[kc + 0][r]      = x0.x; As1[kc + 1][r]      = x0.y; As1[kc + 2][r]      = x0.z; As1[kc + 3][r]      = x0.w;
        As1[kc + 0][r + 64] = x1.x; As1[kc + 1][r + 64] = x1.y; As1[kc + 2][r + 64] = x1.z; As1[kc + 3][r + 64] = x1.w;
        As2[kc + 0][r]      = h0v.x; As2[kc + 1][r]      = h0v.y; As2[kc + 2][r]      = h0v.z; As2[kc + 3][r]      = h0v.w;
        As2[kc + 0][r + 64] = h1v.x; As2[kc + 1][r + 64] = h1v.y; As2[kc + 2][r + 64] = h1v.z; As2[kc + 3][r + 64] = h1v.w;
        for (int i = tid; i < 384; i += 256) {
            int m = (i < 192) ? i : (i - 192);
            const float* src = (i < 192) ? g_Wih1p : g_Whh1p;
            float* Bsd = (i < 192) ? &Bs1[0][0] : &Bs2[0][0];
            int rr = m >> 2, kcc = (m & 3) * 4;
            float4 v = *(const float4*)(src + (size_t)(c0 + rr) * H_ + kt + kcc);
            Bsd[(kcc + 0) * 48 + rr] = v.x;
            Bsd[(kcc + 1) * 48 + rr] = v.y;
            Bsd[(kcc + 2) * 48 + rr] = v.z;
            Bsd[(kcc + 3) * 48 + rr] = v.w;
        }
        __syncthreads();
#pragma unroll
        for (int kk = 0; kk < 16; kk++) {
            float a1[8], a2[8], b1[3], b2[3];
            *(float4*)&a1[0] = *(const float4*)&As1[kk][ty * 8];
            *(float4*)&a1[4] = *(const float4*)&As1[kk][ty * 8 + 4];
            *(float4*)&a2[0] = *(const float4*)&As2[kk][ty * 8];
            *(float4*)&a2[4] = *(const float4*)&As2[kk][ty * 8 + 4];
            b1[0] = Bs1[kk][tx * 3]; b1[1] = Bs1[kk][tx * 3 + 1]; b1[2] = Bs1[kk][tx * 3 + 2];
            b2[0] = Bs2[kk][tx * 3]; b2[1] = Bs2[kk][tx * 3 + 1]; b2[2] = Bs2[kk][tx * 3 + 2];
#pragma unroll
            for (int i = 0; i < 8; i++) {
#pragma unroll
                for (int g = 0; g < 3; g++) {
                    acc_i[i][g] += a1[i] * b1[g];
                    acc_h[i][g] += a2[i] * b2[g];
                }
            }
        }
        __syncthreads();
    }
#pragma unroll
    for (int i = 0; i < 8; i++) {
        int b = bm + ty * 8 + i;
        int j = bh + tx;
        int c = j * 3;
        float gi0 = acc_i[i][0] + g_bi1p[c];
        float gi1 = acc_i[i][1] + g_bi1p[c + 1];
        float gi2 = acc_i[i][2] + g_bi1p[c + 2];
        float gh0 = acc_h[i][0] + g_bh1p[c];
        float gh1 = acc_h[i][1] + g_bh1p[c + 1];
        float gh2 = acc_h[i][2] + g_bh1p[c + 2];
        float rg = sigmoidf_(gi0 + gh0);
        float zg = sigmoidf_(gi1 + gh1);
        float nn = tanhf_(gi2 + rg * gh2);
        float hp = hcur[(size_t)b * H_ + j];
        hnext[(size_t)b * H_ + j] = (1.0f - zg) * nn + zg * hp;
    }
}

// ------------------------- step kernel 3: logits + argmax + token logic -------------------------
__global__ void __launch_bounds__(128) logits_kernel(int p, const float* __restrict__ out_b,
                                                     float* __restrict__ xout,
                                                     float* __restrict__ endp, int step) {
    const float* __restrict__ h = g_h1[p];
    __shared__ float Hs[16 * H_];    // 32 KB
    __shared__ float Ls[16][V_];     // 8 KB
    int b0 = blockIdx.x * 16;
    int tid = threadIdx.x;           // tid == vocab index v

    const float4* src = (const float4*)(h + (size_t)b0 * H_);
    float4* dst = (float4*)Hs;
    for (int i = tid; i < 16 * H_ / 4; i += 128) dst[i] = src[i];
    __syncthreads();

    float acc[16];
#pragma unroll
    for (int r = 0; r < 16; r++) acc[r] = 0.0f;

    for (int k = 0; k < H_; k += 4) {
        float w0 = g_outWt[(k + 0) * V_ + tid];
        float w1 = g_outWt[(k + 1) * V_ + tid];
        float w2 = g_outWt[(k + 2) * V_ + tid];
        float w3 = g_outWt[(k + 3) * V_ + tid];
#pragma unroll
        for (int r = 0; r < 16; r++) {
            float4 hv = *(const float4*)&Hs[r * H_ + k];
            acc[r] += hv.x * w0 + hv.y * w1 + hv.z * w2 + hv.w * w3;
        }
    }
    float bb = out_b[tid];
#pragma unroll
    for (int r = 0; r < 16; r++) Ls[r][tid] = acc[r] + bb;
    __syncthreads();

    if (tid < 16) {
        int b = b0 + tid;
        const float* row = Ls[tid];
        float best = row[0];
        int bi = 0;
        for (int v = 1; v < V_; v++) {
            float xv = row[v];
            if (xv > best) { best = xv; bi = v; }   // first-max, matches jnp.argmax
        }
        int eo = g_eos[b];
        xout[b * MAXLEN + step] = eo ? 0.0f : (float)bi;
        if (!eo && bi == 2) {
            if (endp) endp[b] = (float)(step + 1);
            g_eos[b] = 1;
        }
        g_w[b] = bi;
    }
}

// ------------------------- launch -------------------------
extern "C" void kernel_launch(void* const* d_in, const int* in_sizes, int n_in,
                              void* d_out, int out_size) {
    // Resolve inputs by element count (stable first-match); falls back to
    // positional order. Expected sizes in reference insertion order:
    static const int want[14] = {
        B_ * D_,            // z       4096*512
        V_ * H_,            // emb     128*512
        H_ * D_,            // lat_W   512*512
        H_,                 // lat_b
        TH3 * (H_ + D_),    // Wih0    1536*1024
        TH3 * H_,           // Whh0
        TH3,                // bih0
        TH3,                // bhh0
        TH3 * H_,           // Wih1
        TH3 * H_,           // Whh1
        TH3,                // bih1
        TH3,                // bhh1
        V_ * H_,            // out_W
        V_                  // out_b
    };
    const float* in[14];
    bool used[14] = {};
    bool ok = (n_in >= 14);
    for (int i = 0; i < 14 && ok; i++) {
        int found = -1;
        for (int j = 0; j < 14; j++) {
            if (!used[j] && in_sizes[j] == want[i]) { found = j; break; }
        }
        if (found < 0) { ok = false; break; }
        used[found] = true;
        in[i] = (const float*)d_in[found];
    }
    if (!ok) {
        for (int i = 0; i < 14; i++) in[i] = (const float*)d_in[i];
    }
    const float* z     = in[0];
    const float* emb   = in[1];
    const float* lat_W = in[2];
    const float* lat_b = in[3];
    const float* Wih0  = in[4];
    const float* Whh0  = in[5];
    const float* bih0  = in[6];
    const float* bhh0  = in[7];
    const float* Wih1  = in[8];
    const float* Whh1  = in[9];
    const float* bih1  = in[10];
    const float* bhh1  = in[11];
    const float* out_W = in[12];
    const float* out_b = in[13];

    // Output buffer holds float32 values (per metadata __output__ dtype):
    // output 0: x [B, MAXLEN]; output 1 (if room): end_pads [B] at the tail.
    float* xout = (float*)d_out;
    float* endp = nullptr;
    if (out_size >= B_ * MAXLEN + B_) {
        endp = xout + (out_size - B_);
    }

    // init: permute weights, reset state, precompute h_init / zc0p / T0p
    permute_kernel<<<(TH3 * H_ + 255) / 256, 256>>>(Wih0, Whh0, Wih1, Whh1,
                                                    bih0, bhh0, bih1, bhh1, out_W);
    init_state_kernel<<<(B_ + 255) / 256, 256>>>(xout, endp);
    gemm_init_kernel<<<dim3(H_ / 64, B_ / 64), 256>>>(z, lat_W, lat_b, 0);
    gemm_init_kernel<<<dim3(TH3 / 64, B_ / 64), 256>>>(z, nullptr, nullptr, 1);
    gemm_init_kernel<<<dim3(TH3 / 64, V_ / 64), 256>>>(emb, nullptr, nullptr, 2);

    // 99 decode steps
    for (int s = 1; s < MAXLEN; s++) {
        int p = s & 1;
        layer0_kernel<<<dim3(H_ / 32, B_ / 128), 256>>>(p);
        layer1_kernel<<<dim3(H_ / 16, B_ / 128), 256>>>(p);
        logits_kernel<<<B_ / 16, 128>>>(p, out_b, xout, endp, s);
    }
}